// round 5
// baseline (speedup 1.0000x reference)
#include <cuda_runtime.h>
#include <cuda_fp16.h>
#include <cstdint>

#define SEQ 2048
#define NB 4
#define NH 16
#define HD 64
#define HID 1024
#define MTOT (NB*SEQ)
#define NEG -1e30f
#define ATT_SCALE 0.125f

// ---------------- scratch (device globals; allocation-free rule) ----------
__device__ __half g_q[NB*NH*SEQ*HD];
__device__ __half g_k[NB*NH*SEQ*HD];
__device__ __half g_v[NB*NH*SEQ*HD];
__device__ __half g_att[NB*NH*SEQ*HD];
__device__ __half x_h[(size_t)MTOT*HID];
__device__ __half w_h[4*(size_t)HID*HID];

// ---------------- helpers -------------------------------------------------
__device__ __forceinline__ uint32_t smem_u32(const void* p){
    uint32_t a;
    asm("{ .reg .u64 t; cvta.to.shared.u64 t, %1; cvt.u32.u64 %0, t; }" : "=r"(a) : "l"(p));
    return a;
}
#define SWZ(b) ((b) ^ (((b) >> 3) & 0x70))

__device__ __forceinline__ void cp16s(uint32_t saddr, const void* g){
    asm volatile("cp.async.cg.shared.global [%0], [%1], 16;\n" :: "r"(saddr), "l"(g));
}
__device__ __forceinline__ void cp16z(uint32_t saddr, const void* g, int pred){
    int sz = pred ? 16 : 0;
    asm volatile("cp.async.cg.shared.global [%0], [%1], 16, %2;\n" :: "r"(saddr), "l"(g), "r"(sz));
}
__device__ __forceinline__ void ldm4(uint32_t* r, uint32_t addr){
    asm volatile("ldmatrix.sync.aligned.m8n8.x4.shared.b16 {%0,%1,%2,%3}, [%4];"
        : "=r"(r[0]),"=r"(r[1]),"=r"(r[2]),"=r"(r[3]) : "r"(addr));
}
__device__ __forceinline__ void ldm2(uint32_t* r, uint32_t addr){
    asm volatile("ldmatrix.sync.aligned.m8n8.x2.shared.b16 {%0,%1}, [%2];"
        : "=r"(r[0]),"=r"(r[1]) : "r"(addr));
}
__device__ __forceinline__ void ldm4t(uint32_t* r, uint32_t addr){
    asm volatile("ldmatrix.sync.aligned.m8n8.x4.trans.shared.b16 {%0,%1,%2,%3}, [%4];"
        : "=r"(r[0]),"=r"(r[1]),"=r"(r[2]),"=r"(r[3]) : "r"(addr));
}
__device__ __forceinline__ void mma16(float* c, const uint32_t* a, uint32_t b0, uint32_t b1){
    asm volatile(
      "mma.sync.aligned.m16n8k16.row.col.f32.f16.f16.f32 "
      "{%0,%1,%2,%3},{%4,%5,%6,%7},{%8,%9},{%0,%1,%2,%3};\n"
      : "+f"(c[0]), "+f"(c[1]), "+f"(c[2]), "+f"(c[3])
      : "r"(a[0]), "r"(a[1]), "r"(a[2]), "r"(a[3]), "r"(b0), "r"(b1));
}
// ldmatrix lane address for a 16x16 b16 tile at (row0, k0) in a swizzled
// 64-half (128B) row layout.
__device__ __forceinline__ uint32_t frag_addr(uint32_t tile, int row0, int k0, int lane){
    int r = row0 + (lane & 7) + ((lane >> 3) & 1) * 8;
    int c = k0 + ((lane >> 4) << 3);
    return tile + SWZ((uint32_t)(r * 128 + c * 2));
}

// ---------------------------------------------------------------------------
// fp32 -> fp16 conversion prepass.
// conv_x: x -> x_h.   conv_w: 4 weight matrices in one launch (grid.y = slab).
// ---------------------------------------------------------------------------
__global__ void __launch_bounds__(256)
conv_x(const float* __restrict__ src, int n8)
{
    int i = blockIdx.x * 256 + threadIdx.x;
    if (i < n8){
        float4 v0 = ((const float4*)src)[2*i];
        float4 v1 = ((const float4*)src)[2*i+1];
        __half2 h0 = __floats2half2_rn(v0.x, v0.y);
        __half2 h1 = __floats2half2_rn(v0.z, v0.w);
        __half2 h2 = __floats2half2_rn(v1.x, v1.y);
        __half2 h3 = __floats2half2_rn(v1.z, v1.w);
        uint2 o0, o1;
        o0.x = *(uint32_t*)&h0; o0.y = *(uint32_t*)&h1;
        o1.x = *(uint32_t*)&h2; o1.y = *(uint32_t*)&h3;
        ((uint2*)x_h)[2*i]   = o0;
        ((uint2*)x_h)[2*i+1] = o1;
    }
}

__global__ void __launch_bounds__(256)
conv_w(const float* __restrict__ w0, const float* __restrict__ w1,
       const float* __restrict__ w2, const float* __restrict__ w3)
{
    const int sel = blockIdx.y;
    const float* src = (sel==0) ? w0 : (sel==1 ? w1 : (sel==2 ? w2 : w3));
    __half* dst = w_h + (size_t)sel * (HID*HID);
    int i = blockIdx.x * 256 + threadIdx.x;   // n8 = HID*HID/8 exact multiple
    float4 v0 = ((const float4*)src)[2*i];
    float4 v1 = ((const float4*)src)[2*i+1];
    __half2 h0 = __floats2half2_rn(v0.x, v0.y);
    __half2 h1 = __floats2half2_rn(v0.z, v0.w);
    __half2 h2 = __floats2half2_rn(v1.x, v1.y);
    __half2 h3 = __floats2half2_rn(v1.z, v1.w);
    uint2 o0, o1;
    o0.x = *(uint32_t*)&h0; o0.y = *(uint32_t*)&h1;
    o1.x = *(uint32_t*)&h2; o1.y = *(uint32_t*)&h3;
    ((uint2*)dst)[2*i]   = o0;
    ((uint2*)dst)[2*i+1] = o1;
}

// ---------------------------------------------------------------------------
// fp16 GEMM:  Y[M,N] = A[M,K] @ W[N,K]^T + bias
// BM=128 BN=128 BK=64, 3-stage cp.async, SW128 smem, ldmatrix + mma.m16n8k16.
// qkv_mode=1: A = x_h, z selects W slab / bias / g_q|k|v scatter (half),
//             epilogue staged through smem for coalesced 16B global stores.
// qkv_mode=0: A = gather from g_att (half, [B,H,S,D]), W slab 3, fp32 out + bias.
// ---------------------------------------------------------------------------
#define GBK 64
#define A_BYT (128*128)         // 128 rows x 128B
#define STG   (2*A_BYT)         // A + B per stage
#define NSTG  3
#define NK    (HID/GBK)         // 16

__global__ void __launch_bounds__(256, 2)
gemm_h(const float* __restrict__ b0_, const float* __restrict__ b1_,
       const float* __restrict__ b2_, float* __restrict__ Yout, int qkv_mode)
{
    extern __shared__ char smem[];
    const uint32_t sb0 = smem_u32(smem);
    const int tid = threadIdx.x, lane = tid & 31, warp = tid >> 5;
    const int wm = warp & 3, wn = warp >> 2;            // 4m x 2n warps
    const int n0 = blockIdx.x * 128, m0 = blockIdx.y * 128;
    const int z  = qkv_mode ? blockIdx.z : 3;
    const __half* W    = w_h + (size_t)z * (HID*HID);
    const float* bias  = qkv_mode ? (z==0 ? b0_ : (z==1 ? b1_ : b2_)) : b0_;
    __half* dsth       = qkv_mode ? (z==0 ? g_q : (z==1 ? g_k : g_v)) : nullptr;

    float c[2][8][4];
    #pragma unroll
    for (int i = 0; i < 2; i++)
      #pragma unroll
      for (int j = 0; j < 8; j++)
        #pragma unroll
        for (int v = 0; v < 4; v++) c[i][j][v] = 0.f;

    auto load_chunk = [&](int ch, int slot){
        const int k0 = ch * GBK;
        const uint32_t uA = sb0 + slot * STG;
        const uint32_t uB = uA + A_BYT;
        #pragma unroll
        for (int i = 0; i < 4; i++){                    // A: 1024 16B ops
            int op = tid + i * 256;
            int row = op >> 3, at = op & 7;
            const __half* src;
            if (qkv_mode){
                src = x_h + (size_t)(m0 + row) * HID + k0 + at * 8;
            } else {
                int m = m0 + row, kg = k0 + at * 8;
                src = g_att + ((size_t)(((m >> 11) * NH + (kg >> 6)) * SEQ + (m & 2047)) * HD + (kg & 63));
            }
            cp16s(uA + SWZ((uint32_t)(row * 128 + at * 16)), src);
        }
        #pragma unroll
        for (int i = 0; i < 4; i++){                    // B: 1024 16B ops
            int op = tid + i * 256;
            int row = op >> 3, at = op & 7;
            cp16s(uB + SWZ((uint32_t)(row * 128 + at * 16)),
                  W + (size_t)(n0 + row) * HID + k0 + at * 8);
        }
        asm volatile("cp.async.commit_group;\n");
    };

    load_chunk(0, 0);
    load_chunk(1, 1);

    for (int ch = 0; ch < NK; ch++){
        if (ch + 2 < NK) load_chunk(ch + 2, (ch + 2) % NSTG);
        const int rem = NK - 1 - ch;
        if      (rem >= 2) asm volatile("cp.async.wait_group 2;\n");
        else if (rem == 1) asm volatile("cp.async.wait_group 1;\n");
        else               asm volatile("cp.async.wait_group 0;\n");
        __syncthreads();

        const uint32_t uA = sb0 + (ch % NSTG) * STG;
        const uint32_t uB = uA + A_BYT;
        #pragma unroll
        for (int ks = 0; ks < 4; ks++){
            uint32_t a[2][4];
            ldm4(a[0], frag_addr(uA, wm*32,      ks*16, lane));
            ldm4(a[1], frag_addr(uA, wm*32 + 16, ks*16, lane));
            uint32_t b[4][4];
            #pragma unroll
            for (int nb = 0; nb < 4; nb++)
                ldm4(b[nb], frag_addr(uB, wn*64 + nb*16, ks*16, lane));
            #pragma unroll
            for (int nt = 0; nt < 8; nt++){
                const int nb = nt >> 1, hi = nt & 1;
                mma16(c[0][nt], a[0], b[nb][hi], b[nb][2+hi]);
                mma16(c[1][nt], a[1], b[nb][hi], b[nb][2+hi]);
            }
        }
        __syncthreads();
    }

    if (qkv_mode){
        // ---- staged epilogue: frags -> smem (half) -> coalesced 16B stores
        __half* stg = (__half*)smem;                    // 128 x 136 halves
        #pragma unroll
        for (int nt = 0; nt < 8; nt++){
            const int cn = wn*64 + nt*8 + 2*(lane & 3);
            float2 bv = *(const float2*)(bias + n0 + cn);
            #pragma unroll
            for (int mt = 0; mt < 2; mt++){
                const int r0 = wm*32 + mt*16 + (lane >> 2);
                #pragma unroll
                for (int hf = 0; hf < 2; hf++){
                    *(__half2*)&stg[(r0 + hf*8) * 136 + cn] =
                        __floats2half2_rn(c[mt][nt][hf*2] + bv.x,
                                          c[mt][nt][hf*2+1] + bv.y);
                }
            }
        }
        __syncthreads();
        #pragma unroll
        for (int i = 0; i < 8; i++){                    // 2048 16B slots
            int op = tid + i * 256;
            int row = op >> 4, c16 = op & 15;
            int m = m0 + row, n = n0 + c16 * 8;
            uint4 val = *(const uint4*)&stg[row * 136 + c16 * 8];
            *(uint4*)(dsth + (((size_t)((m >> 11) * NH + (n >> 6)) * SEQ + (m & 2047)) * HD + (n & 63))) = val;
        }
    } else {
        // fp32 output, already sector-efficient (4 lanes cover a 32B sector)
        #pragma unroll
        for (int nt = 0; nt < 8; nt++){
            const int nn = n0 + wn*64 + nt*8 + 2*(lane & 3);
            float2 bv = *(const float2*)(bias + nn);
            #pragma unroll
            for (int mt = 0; mt < 2; mt++){
                const int rr = m0 + wm*32 + mt*16 + (lane >> 2);
                #pragma unroll
                for (int hf = 0; hf < 2; hf++){
                    const int m = rr + hf*8;
                    *(float2*)(Yout + (size_t)m * HID + nn) =
                        make_float2(c[mt][nt][hf*2] + bv.x, c[mt][nt][hf*2+1] + bv.y);
                }
            }
        }
    }
}

// ---------------------------------------------------------------------------
// Band attention, fp16 mma: one block per (64-row tile, head, batch).
// Scores kept in fp32 registers; softmax via quad shuffles + small smem.
// ---------------------------------------------------------------------------
#define PS_STR 168
#define QS_OFF 0
#define KS_OFF 8192
#define VS_OFF 26624
#define PS_OFF 45056
#define RED_OFF 66560
#define ATT_SMEM (RED_OFF + 1024)

__global__ void __launch_bounds__(256, 3)
attn_band()
{
    extern __shared__ char smem[];
    const uint32_t sb = smem_u32(smem);
    const uint32_t uQ = sb + QS_OFF, uK = sb + KS_OFF, uV = sb + VS_OFF;
    __half* Ps  = (__half*)(smem + PS_OFF);
    float* mred = (float*)(smem + RED_OFF);      // [2][64]
    float* sred = mred + 128;                    // [2][64]

    const int tid = threadIdx.x, lane = tid & 31, warp = tid >> 5;
    const int q = lane & 3;
    const int t = blockIdx.x, h = blockIdx.y, b = blockIdx.z;
    const int i0 = t * 64;
    const int nglob = (t == 0) ? 0 : 4;
    const int jlo   = (t == 0) ? 0 : (i0 - 32);
    const int jhi   = min(SEQ - 1, i0 + 95);
    const int NC    = nglob + (jhi - jlo + 1);
    const size_t base = ((size_t)(b * NH + h)) * SEQ * HD;

    // ---- load Q (64 rows) ----
    #pragma unroll
    for (int i = 0; i < 2; i++){
        int op = tid + i * 256;
        int row = op >> 3, at = op & 7;
        cp16s(uQ + SWZ((uint32_t)(row * 128 + at * 16)),
              g_q + base + (size_t)(i0 + row) * HD + at * 8);
    }
    // ---- load K/V (144 rows each, zero-fill beyond NC) ----
    #pragma unroll
    for (int i = 0; i < 9; i++){
        int op = tid + i * 256;
        int cc = op >> 4, at8 = op & 15;
        int at = at8 & 7;
        int isK = (at8 < 8);
        int valid = (cc < NC);
        int j = valid ? ((cc < nglob) ? cc : jlo + (cc - nglob)) : 0;
        const __half* src = (isK ? g_k : g_v) + base + (size_t)j * HD + at * 8;
        cp16z((isK ? uK : uV) + SWZ((uint32_t)(cc * 128 + at * 16)), src, valid);
    }
    asm volatile("cp.async.commit_group;\ncp.async.wait_group 0;\n");
    __syncthreads();

    // ---- scores ----
    {
        const int wm = warp >> 1, wn = warp & 1;
        const int r_lo = wm*16 + (lane >> 2);
        float cs[9][4];
        #pragma unroll
        for (int nt = 0; nt < 9; nt++)
            #pragma unroll
            for (int v = 0; v < 4; v++) cs[nt][v] = 0.f;

        #pragma unroll
        for (int ks = 0; ks < 4; ks++){
            uint32_t qa[4];
            ldm4(qa, frag_addr(uQ, wm*16, ks*16, lane));
            uint32_t kb[4][4];
            #pragma unroll
            for (int nb = 0; nb < 4; nb++)
                ldm4(kb[nb], frag_addr(uK, wn*72 + nb*16, ks*16, lane));
            uint32_t k2[2];
            {
                int i2 = lane & 15;
                int rr = wn*72 + 64 + (i2 & 7);
                int cc = ks*16 + ((i2 >> 3) << 3);
                ldm2(k2, uK + SWZ((uint32_t)(rr * 128 + cc * 2)));
            }
            #pragma unroll
            for (int nt = 0; nt < 8; nt++){
                const int nb = nt >> 1, hi = nt & 1;
                mma16(cs[nt], qa, kb[nb][hi], kb[nb][2+hi]);
            }
            mma16(cs[8], qa, k2[0], k2[1]);
        }

        // mask + scale in regs
        #pragma unroll
        for (int nt = 0; nt < 9; nt++)
            #pragma unroll
            for (int v = 0; v < 4; v++){
                const int r  = r_lo + ((v >= 2) ? 8 : 0);
                const int cc = wn*72 + nt*8 + 2*q + (v & 1);
                float sv = NEG;
                if (cc < NC){
                    int j = (cc < nglob) ? cc : jlo + (cc - nglob);
                    int i = i0 + r;
                    int d = i - j; if (d < 0) d = -d;
                    if (j < 4 || d <= 32) sv = cs[nt][v] * ATT_SCALE;
                }
                cs[nt][v] = sv;
            }

        // row max (quad reduce)
        float mlo = NEG, mhi = NEG;
        #pragma unroll
        for (int nt = 0; nt < 9; nt++){
            mlo = fmaxf(mlo, fmaxf(cs[nt][0], cs[nt][1]));
            mhi = fmaxf(mhi, fmaxf(cs[nt][2], cs[nt][3]));
        }
        mlo = fmaxf(mlo, __shfl_xor_sync(0xffffffffu, mlo, 1));
        mlo = fmaxf(mlo, __shfl_xor_sync(0xffffffffu, mlo, 2));
        mhi = fmaxf(mhi, __shfl_xor_sync(0xffffffffu, mhi, 1));
        mhi = fmaxf(mhi, __shfl_xor_sync(0xffffffffu, mhi, 2));
        if (q == 0){
            mred[wn*64 + r_lo]     = mlo;
            mred[wn*64 + r_lo + 8] = mhi;
        }
        __syncthreads();
        mlo = fmaxf(mred[r_lo],     mred[64 + r_lo]);
        mhi = fmaxf(mred[r_lo + 8], mred[64 + r_lo + 8]);

        // exp, store P (half), row sums
        float slo = 0.f, shi = 0.f;
        #pragma unroll
        for (int nt = 0; nt < 9; nt++){
            const int cc0 = wn*72 + nt*8 + 2*q;
            float p0 = __expf(cs[nt][0] - mlo);
            float p1 = __expf(cs[nt][1] - mlo);
            float p2 = __expf(cs[nt][2] - mhi);
            float p3 = __expf(cs[nt][3] - mhi);
            slo += p0 + p1; shi += p2 + p3;
            *(__half2*)&Ps[(r_lo    ) * PS_STR + cc0] = __floats2half2_rn(p0, p1);
            *(__half2*)&Ps[(r_lo + 8) * PS_STR + cc0] = __floats2half2_rn(p2, p3);
        }
        slo += __shfl_xor_sync(0xffffffffu, slo, 1);
        slo += __shfl_xor_sync(0xffffffffu, slo, 2);
        shi += __shfl_xor_sync(0xffffffffu, shi, 1);
        shi += __shfl_xor_sync(0xffffffffu, shi, 2);
        if (q == 0){
            sred[wn*64 + r_lo]     = slo;
            sred[wn*64 + r_lo + 8] = shi;
        }
    }
    __syncthreads();

    // ---- PV ----
    {
        const int wm2 = warp >> 1, wn2 = warp & 1;
        const int r_lo = wm2*16 + (lane >> 2);
        float co[4][4];
        #pragma unroll
        for (int nt = 0; nt < 4; nt++)
            #pragma unroll
            for (int v = 0; v < 4; v++) co[nt][v] = 0.f;

        #pragma unroll
        for (int ks = 0; ks < 9; ks++){
            const int k0 = ks * 16;
            uint32_t pa[4];
            pa[0] = *(const uint32_t*)&Ps[(r_lo    ) * PS_STR + k0 + 2*q];
            pa[1] = *(const uint32_t*)&Ps[(r_lo + 8) * PS_STR + k0 + 2*q];
            pa[2] = *(const uint32_t*)&Ps[(r_lo    ) * PS_STR + k0 + 8 + 2*q];
            pa[3] = *(const uint32_t*)&Ps[(r_lo + 8) * PS_STR + k0 + 8 + 2*q];
            uint32_t vb[2][4];
            #pragma unroll
            for (int db = 0; db < 2; db++){
                int m_ = lane >> 3;
                int j  = k0 + (lane & 7) + (m_ & 1) * 8;
                int dc = wn2*32 + db*16 + (m_ >> 1) * 8;
                ldm4t(vb[db], uV + SWZ((uint32_t)(j * 128 + dc * 2)));
            }
            #pragma unroll
            for (int nt = 0; nt < 4; nt++){
                const int db = nt >> 1, hi = nt & 1;
                mma16(co[nt], pa, vb[db][hi*2], vb[db][hi*2 + 1]);
            }
        }

        const float rlo = 1.f / (sred[r_lo]     + sred[64 + r_lo]);
        const float rhi = 1.f / (sred[r_lo + 8] + sred[64 + r_lo + 8]);
        #pragma unroll
        for (int nt = 0; nt < 4; nt++){
            const int d0 = wn2*32 + nt*8 + 2*q;
            #pragma unroll
            for (int hf = 0; hf < 2; hf++){
                const int r = r_lo + hf*8;
                const int i = i0 + r;
                if (i >= 4){
                    float sc = hf ? rhi : rlo;
                    __half2 hv = __floats2half2_rn(co[nt][hf*2] * sc, co[nt][hf*2+1] * sc);
                    *(__half2*)(g_att + base + (size_t)i * HD + d0) = hv;
                }
            }
        }
    }
}

// ---------------------------------------------------------------------------
// Global rows (i < 4): dense attention over all 2048 cols, fp32 math.
// One block per (head, batch); all 4 rows share the K/V read.
// ---------------------------------------------------------------------------
__global__ void __launch_bounds__(256)
attn_global()
{
    __shared__ float qs[4][HD];
    __shared__ float s[4][SEQ];
    __shared__ float red[256];
    __shared__ float mxv[4], riv[4];
    const int tid = threadIdx.x;
    const int h = blockIdx.x, b = blockIdx.y;
    const size_t base = ((size_t)(b * NH + h)) * SEQ * HD;

    // load 4 q rows
    qs[tid >> 6][tid & 63] = __half2float(g_q[base + (size_t)(tid >> 6) * HD + (tid & 63)]);
    __syncthreads();

    // scores: each thread handles several j columns for all 4 rows
    for (int j = tid; j < SEQ; j += 256){
        const __half2* kr = (const __half2*)(g_k + base + (size_t)j * HD);
        float a0 = 0.f, a1 = 0.f, a2 = 0.f, a3 = 0.f;
        #pragma unroll
        for (int dd = 0; dd < 32; dd++){
            float2 kv = __half22float2(kr[dd]);
            a0 += qs[0][2*dd] * kv.x + qs[0][2*dd+1] * kv.y;
            a1 += qs[1][2*dd] * kv.x + qs[1][2*dd+1] * kv.y;
            a2 += qs[2][2*dd] * kv.x + qs[2][2*dd+1] * kv.y;
            a3 += qs[3][2*dd] * kv.x + qs[3][2*dd+1] * kv.y;
        }
        s[0][j] = a0 * ATT_SCALE;
        s[1][j] = a1 * ATT_SCALE;
        s[2][j] = a2 * ATT_SCALE;
        s[3][j] = a3 * ATT_SCALE;
    }
    __syncthreads();

    // softmax per row (sequential over 4 rows; block-wide reductions)
    for (int r = 0; r < 4; r++){
        float lm = NEG;
        for (int j = tid; j < SEQ; j += 256) lm = fmaxf(lm, s[r][j]);
        red[tid] = lm; __syncthreads();
        for (int off = 128; off; off >>= 1){
            if (tid < off) red[tid] = fmaxf(red[tid], red[tid + off]);
            __syncthreads();
        }
        if (tid == 0) mxv[r] = red[0];
        __syncthreads();
        const float mx = mxv[r];

        float ls = 0.f;
        for (int j = tid; j < SEQ; j += 256){
            float p = __expf(s[r][j] - mx); s[r][j] = p; ls += p;
        }
        red[tid] = ls; __syncthreads();
        for (int off = 128; off; off >>= 1){
            if (tid < off) red[tid] += red[tid + off];
            __syncthreads();
        }
        if (tid == 0) riv[r] = 1.f / red[0];
        __syncthreads();
    }

    // PV: thread (r, d) = (tid>>6, tid&63); V row broadcast across the 4 r's
    const int r = tid >> 6, d = tid & 63;
    float acc = 0.f;
    const __half* vb = g_v + base + d;
    #pragma unroll 8
    for (int j = 0; j < SEQ; j++)
        acc += s[r][j] * __half2float(vb[(size_t)j * HD]);
    g_att[base + (size_t)r * HD + d] = __float2half_rn(acc * riv[r]);
}

// ---------------------------------------------------------------------------
extern "C" void kernel_launch(void* const* d_in, const int* in_sizes, int n_in,
                              void* d_out, int out_size)
{
    const float* x  = (const float*)d_in[0];
    const float* Wq = (const float*)d_in[1];
    const float* bq = (const float*)d_in[2];
    const float* Wk = (const float*)d_in[3];
    const float* bk = (const float*)d_in[4];
    const float* Wv = (const float*)d_in[5];
    const float* bv = (const float*)d_in[6];
    const float* Wo = (const float*)d_in[7];
    const float* bo = (const float*)d_in[8];
    float* out = (float*)d_out;

    const int gsm = NSTG * STG;     // 98304 B
    cudaFuncSetAttribute(gemm_h,    cudaFuncAttributeMaxDynamicSharedMemorySize, gsm);
    cudaFuncSetAttribute(attn_band, cudaFuncAttributeMaxDynamicSharedMemorySize, ATT_SMEM);

    // launch 0: x conversion
    conv_x<<<(MTOT*HID/8 + 255)/256, 256>>>(x, MTOT*HID/8);
    // launch 1: all 4 weight conversions
    conv_w<<<dim3(HID*HID/8/256, 4), 256>>>(Wq, Wk, Wv, Wo);
    // launch 2: fused QKV projections
    gemm_h<<<dim3(HID/128, MTOT/128, 3), 256, gsm>>>(bq, bk, bv, nullptr, 1);
    // launch 3-4: attention
    attn_band<<<dim3(SEQ/64, NH, NB), 256, ATT_SMEM>>>();
    attn_global<<<dim3(NH, NB), 256>>>();
    // launch 5: output projection  (ncu -s 5 -c 1 captures this one)
    gemm_h<<<dim3(HID/128, MTOT/128, 1), 256, gsm>>>(bo, nullptr, nullptr, out, 0);
}

// round 6
// speedup vs baseline: 1.0263x; 1.0263x over previous
#include <cuda_runtime.h>
#include <cuda_fp16.h>
#include <cstdint>

#define SEQ 2048
#define NB 4
#define NH 16
#define HD 64
#define HID 1024
#define MTOT (NB*SEQ)
#define NEG -1e30f
#define ATT_SCALE 0.125f

// ---------------- scratch (device globals; allocation-free rule) ----------
__device__ __half g_q[NB*NH*SEQ*HD];
__device__ __half g_k[NB*NH*SEQ*HD];
__device__ __half g_v[NB*NH*SEQ*HD];
__device__ __half g_att[NB*NH*SEQ*HD];
__device__ __half x_h[(size_t)MTOT*HID];
__device__ __half w_h[4*(size_t)HID*HID];

// ---------------- helpers -------------------------------------------------
__device__ __forceinline__ uint32_t smem_u32(const void* p){
    uint32_t a;
    asm("{ .reg .u64 t; cvta.to.shared.u64 t, %1; cvt.u32.u64 %0, t; }" : "=r"(a) : "l"(p));
    return a;
}
#define SWZ(b) ((b) ^ (((b) >> 3) & 0x70))

__device__ __forceinline__ void cp16s(uint32_t saddr, const void* g){
    asm volatile("cp.async.cg.shared.global [%0], [%1], 16;\n" :: "r"(saddr), "l"(g));
}
__device__ __forceinline__ void cp16z(uint32_t saddr, const void* g, int pred){
    int sz = pred ? 16 : 0;
    asm volatile("cp.async.cg.shared.global [%0], [%1], 16, %2;\n" :: "r"(saddr), "l"(g), "r"(sz));
}
__device__ __forceinline__ void ldm4(uint32_t* r, uint32_t addr){
    asm volatile("ldmatrix.sync.aligned.m8n8.x4.shared.b16 {%0,%1,%2,%3}, [%4];"
        : "=r"(r[0]),"=r"(r[1]),"=r"(r[2]),"=r"(r[3]) : "r"(addr));
}
__device__ __forceinline__ void ldm2(uint32_t* r, uint32_t addr){
    asm volatile("ldmatrix.sync.aligned.m8n8.x2.shared.b16 {%0,%1}, [%2];"
        : "=r"(r[0]),"=r"(r[1]) : "r"(addr));
}
__device__ __forceinline__ void ldm4t(uint32_t* r, uint32_t addr){
    asm volatile("ldmatrix.sync.aligned.m8n8.x4.trans.shared.b16 {%0,%1,%2,%3}, [%4];"
        : "=r"(r[0]),"=r"(r[1]),"=r"(r[2]),"=r"(r[3]) : "r"(addr));
}
__device__ __forceinline__ void mma16(float* c, const uint32_t* a, uint32_t b0, uint32_t b1){
    asm volatile(
      "mma.sync.aligned.m16n8k16.row.col.f32.f16.f16.f32 "
      "{%0,%1,%2,%3},{%4,%5,%6,%7},{%8,%9},{%0,%1,%2,%3};\n"
      : "+f"(c[0]), "+f"(c[1]), "+f"(c[2]), "+f"(c[3])
      : "r"(a[0]), "r"(a[1]), "r"(a[2]), "r"(a[3]), "r"(b0), "r"(b1));
}
// ldmatrix lane address for a 16x16 b16 tile at (row0, k0) in a swizzled
// 64-half (128B) row layout.
__device__ __forceinline__ uint32_t frag_addr(uint32_t tile, int row0, int k0, int lane){
    int r = row0 + (lane & 7) + ((lane >> 3) & 1) * 8;
    int c = k0 + ((lane >> 4) << 3);
    return tile + SWZ((uint32_t)(r * 128 + c * 2));
}

// ---------------------------------------------------------------------------
// fp32 -> fp16 conversion prepass.
// ---------------------------------------------------------------------------
__global__ void __launch_bounds__(256)
conv_x(const float* __restrict__ src, int n8)
{
    int i = blockIdx.x * 256 + threadIdx.x;
    if (i < n8){
        float4 v0 = ((const float4*)src)[2*i];
        float4 v1 = ((const float4*)src)[2*i+1];
        __half2 h0 = __floats2half2_rn(v0.x, v0.y);
        __half2 h1 = __floats2half2_rn(v0.z, v0.w);
        __half2 h2 = __floats2half2_rn(v1.x, v1.y);
        __half2 h3 = __floats2half2_rn(v1.z, v1.w);
        uint2 o0, o1;
        o0.x = *(uint32_t*)&h0; o0.y = *(uint32_t*)&h1;
        o1.x = *(uint32_t*)&h2; o1.y = *(uint32_t*)&h3;
        ((uint2*)x_h)[2*i]   = o0;
        ((uint2*)x_h)[2*i+1] = o1;
    }
}

__global__ void __launch_bounds__(256)
conv_w(const float* __restrict__ w0, const float* __restrict__ w1,
       const float* __restrict__ w2, const float* __restrict__ w3)
{
    const int sel = blockIdx.y;
    const float* src = (sel==0) ? w0 : (sel==1 ? w1 : (sel==2 ? w2 : w3));
    __half* dst = w_h + (size_t)sel * (HID*HID);
    int i = blockIdx.x * 256 + threadIdx.x;
    float4 v0 = ((const float4*)src)[2*i];
    float4 v1 = ((const float4*)src)[2*i+1];
    __half2 h0 = __floats2half2_rn(v0.x, v0.y);
    __half2 h1 = __floats2half2_rn(v0.z, v0.w);
    __half2 h2 = __floats2half2_rn(v1.x, v1.y);
    __half2 h3 = __floats2half2_rn(v1.z, v1.w);
    uint2 o0, o1;
    o0.x = *(uint32_t*)&h0; o0.y = *(uint32_t*)&h1;
    o1.x = *(uint32_t*)&h2; o1.y = *(uint32_t*)&h3;
    ((uint2*)dst)[2*i]   = o0;
    ((uint2*)dst)[2*i+1] = o1;
}

// ---------------------------------------------------------------------------
// fp16 GEMM:  Y[M,N] = A[M,K] @ W[N,K]^T + bias
// BM=128 BN=256 BK=64, 512 threads (16 warps, 4m x 4n, warp tile 32x64),
// 3-stage cp.async, SW128 smem, ldmatrix + mma.m16n8k16.
// qkv_mode=1: A = x_h, z selects W slab / bias / g_q|k|v scatter (half),
//             epilogue staged through smem for coalesced 16B global stores.
// qkv_mode=0: A = gather from g_att (half, [B,H,S,D]), W slab 3, fp32 out + bias.
// ---------------------------------------------------------------------------
#define GBK 64
#define GBN 256
#define A_BYT (128*128)         // 128 rows x 128B = 16 KB
#define B_BYT (GBN*128)         // 256 rows x 128B = 32 KB
#define STG   (A_BYT + B_BYT)   // 48 KB per stage
#define NSTG  3
#define NK    (HID/GBK)         // 16
#define GT    512

__global__ void __launch_bounds__(GT, 1)
gemm_h(const float* __restrict__ b0_, const float* __restrict__ b1_,
       const float* __restrict__ b2_, float* __restrict__ Yout, int qkv_mode)
{
    extern __shared__ char smem[];
    const uint32_t sb0 = smem_u32(smem);
    const int tid = threadIdx.x, lane = tid & 31, warp = tid >> 5;
    const int wm = warp & 3, wn = warp >> 2;            // 4m x 4n warps
    const int n0 = blockIdx.x * GBN, m0 = blockIdx.y * 128;
    const int z  = qkv_mode ? blockIdx.z : 3;
    const __half* W    = w_h + (size_t)z * (HID*HID);
    const float* bias  = qkv_mode ? (z==0 ? b0_ : (z==1 ? b1_ : b2_)) : b0_;
    __half* dsth       = qkv_mode ? (z==0 ? g_q : (z==1 ? g_k : g_v)) : nullptr;

    float c[2][8][4];
    #pragma unroll
    for (int i = 0; i < 2; i++)
      #pragma unroll
      for (int j = 0; j < 8; j++)
        #pragma unroll
        for (int v = 0; v < 4; v++) c[i][j][v] = 0.f;

    auto load_chunk = [&](int ch, int slot){
        const int k0 = ch * GBK;
        const uint32_t uA = sb0 + slot * STG;
        const uint32_t uB = uA + A_BYT;
        #pragma unroll
        for (int i = 0; i < 2; i++){                    // A: 1024 16B ops
            int op = tid + i * GT;
            int row = op >> 3, at = op & 7;
            const __half* src;
            if (qkv_mode){
                src = x_h + (size_t)(m0 + row) * HID + k0 + at * 8;
            } else {
                int m = m0 + row, kg = k0 + at * 8;
                src = g_att + ((size_t)(((m >> 11) * NH + (kg >> 6)) * SEQ + (m & 2047)) * HD + (kg & 63));
            }
            cp16s(uA + SWZ((uint32_t)(row * 128 + at * 16)), src);
        }
        #pragma unroll
        for (int i = 0; i < 4; i++){                    // B: 2048 16B ops
            int op = tid + i * GT;
            int row = op >> 3, at = op & 7;
            cp16s(uB + SWZ((uint32_t)(row * 128 + at * 16)),
                  W + (size_t)(n0 + row) * HID + k0 + at * 8);
        }
        asm volatile("cp.async.commit_group;\n");
    };

    load_chunk(0, 0);
    load_chunk(1, 1);

    for (int ch = 0; ch < NK; ch++){
        if (ch + 2 < NK) load_chunk(ch + 2, (ch + 2) % NSTG);
        const int rem = NK - 1 - ch;
        if      (rem >= 2) asm volatile("cp.async.wait_group 2;\n");
        else if (rem == 1) asm volatile("cp.async.wait_group 1;\n");
        else               asm volatile("cp.async.wait_group 0;\n");
        __syncthreads();

        const uint32_t uA = sb0 + (ch % NSTG) * STG;
        const uint32_t uB = uA + A_BYT;
        #pragma unroll
        for (int ks = 0; ks < 4; ks++){
            uint32_t a[2][4];
            ldm4(a[0], frag_addr(uA, wm*32,      ks*16, lane));
            ldm4(a[1], frag_addr(uA, wm*32 + 16, ks*16, lane));
            uint32_t b[4][4];
            #pragma unroll
            for (int nb = 0; nb < 4; nb++)
                ldm4(b[nb], frag_addr(uB, wn*64 + nb*16, ks*16, lane));
            #pragma unroll
            for (int nt = 0; nt < 8; nt++){
                const int nb = nt >> 1, hi = nt & 1;
                mma16(c[0][nt], a[0], b[nb][hi], b[nb][2+hi]);
                mma16(c[1][nt], a[1], b[nb][hi], b[nb][2+hi]);
            }
        }
        __syncthreads();
    }

    if (qkv_mode){
        // ---- staged epilogue: frags -> smem (half) -> coalesced 16B stores
        __half* stg = (__half*)smem;                    // 128 x 264 halves
        #pragma unroll
        for (int nt = 0; nt < 8; nt++){
            const int cn = wn*64 + nt*8 + 2*(lane & 3);
            float2 bv = *(const float2*)(bias + n0 + cn);
            #pragma unroll
            for (int mt = 0; mt < 2; mt++){
                const int r0 = wm*32 + mt*16 + (lane >> 2);
                #pragma unroll
                for (int hf = 0; hf < 2; hf++){
                    *(__half2*)&stg[(r0 + hf*8) * 264 + cn] =
                        __floats2half2_rn(c[mt][nt][hf*2] + bv.x,
                                          c[mt][nt][hf*2+1] + bv.y);
                }
            }
        }
        __syncthreads();
        #pragma unroll
        for (int i = 0; i < 8; i++){                    // 4096 16B slots
            int op = tid + i * GT;
            int row = op >> 5, c32 = op & 31;
            int m = m0 + row, n = n0 + c32 * 8;
            uint4 val = *(const uint4*)&stg[row * 264 + c32 * 8];
            *(uint4*)(dsth + (((size_t)((m >> 11) * NH + (n >> 6)) * SEQ + (m & 2047)) * HD + (n & 63))) = val;
        }
    } else {
        // fp32 output, sector-efficient float2 stores
        #pragma unroll
        for (int nt = 0; nt < 8; nt++){
            const int nn = n0 + wn*64 + nt*8 + 2*(lane & 3);
            float2 bv = *(const float2*)(bias + nn);
            #pragma unroll
            for (int mt = 0; mt < 2; mt++){
                const int rr = m0 + wm*32 + mt*16 + (lane >> 2);
                #pragma unroll
                for (int hf = 0; hf < 2; hf++){
                    const int m = rr + hf*8;
                    *(float2*)(Yout + (size_t)m * HID + nn) =
                        make_float2(c[mt][nt][hf*2] + bv.x, c[mt][nt][hf*2+1] + bv.y);
                }
            }
        }
    }
}

// ---------------------------------------------------------------------------
// Band attention, fp16 mma: one block per (64-row tile, head, batch).
// ---------------------------------------------------------------------------
#define PS_STR 168
#define QS_OFF 0
#define KS_OFF 8192
#define VS_OFF 26624
#define PS_OFF 45056
#define RED_OFF 66560
#define ATT_SMEM (RED_OFF + 1024)

__global__ void __launch_bounds__(256, 3)
attn_band()
{
    extern __shared__ char smem[];
    const uint32_t sb = smem_u32(smem);
    const uint32_t uQ = sb + QS_OFF, uK = sb + KS_OFF, uV = sb + VS_OFF;
    __half* Ps  = (__half*)(smem + PS_OFF);
    float* mred = (float*)(smem + RED_OFF);      // [2][64]
    float* sred = mred + 128;                    // [2][64]

    const int tid = threadIdx.x, lane = tid & 31, warp = tid >> 5;
    const int q = lane & 3;
    const int t = blockIdx.x, h = blockIdx.y, b = blockIdx.z;
    const int i0 = t * 64;
    const int nglob = (t == 0) ? 0 : 4;
    const int jlo   = (t == 0) ? 0 : (i0 - 32);
    const int jhi   = min(SEQ - 1, i0 + 95);
    const int NC    = nglob + (jhi - jlo + 1);
    const size_t base = ((size_t)(b * NH + h)) * SEQ * HD;

    #pragma unroll
    for (int i = 0; i < 2; i++){
        int op = tid + i * 256;
        int row = op >> 3, at = op & 7;
        cp16s(uQ + SWZ((uint32_t)(row * 128 + at * 16)),
              g_q + base + (size_t)(i0 + row) * HD + at * 8);
    }
    #pragma unroll
    for (int i = 0; i < 9; i++){
        int op = tid + i * 256;
        int cc = op >> 4, at8 = op & 15;
        int at = at8 & 7;
        int isK = (at8 < 8);
        int valid = (cc < NC);
        int j = valid ? ((cc < nglob) ? cc : jlo + (cc - nglob)) : 0;
        const __half* src = (isK ? g_k : g_v) + base + (size_t)j * HD + at * 8;
        cp16z((isK ? uK : uV) + SWZ((uint32_t)(cc * 128 + at * 16)), src, valid);
    }
    asm volatile("cp.async.commit_group;\ncp.async.wait_group 0;\n");
    __syncthreads();

    // ---- scores ----
    {
        const int wm = warp >> 1, wn = warp & 1;
        const int r_lo = wm*16 + (lane >> 2);
        float cs[9][4];
        #pragma unroll
        for (int nt = 0; nt < 9; nt++)
            #pragma unroll
            for (int v = 0; v < 4; v++) cs[nt][v] = 0.f;

        #pragma unroll
        for (int ks = 0; ks < 4; ks++){
            uint32_t qa[4];
            ldm4(qa, frag_addr(uQ, wm*16, ks*16, lane));
            uint32_t kb[4][4];
            #pragma unroll
            for (int nb = 0; nb < 4; nb++)
                ldm4(kb[nb], frag_addr(uK, wn*72 + nb*16, ks*16, lane));
            uint32_t k2[2];
            {
                int i2 = lane & 15;
                int rr = wn*72 + 64 + (i2 & 7);
                int cc = ks*16 + ((i2 >> 3) << 3);
                ldm2(k2, uK + SWZ((uint32_t)(rr * 128 + cc * 2)));
            }
            #pragma unroll
            for (int nt = 0; nt < 8; nt++){
                const int nb = nt >> 1, hi = nt & 1;
                mma16(cs[nt], qa, kb[nb][hi], kb[nb][2+hi]);
            }
            mma16(cs[8], qa, k2[0], k2[1]);
        }

        #pragma unroll
        for (int nt = 0; nt < 9; nt++)
            #pragma unroll
            for (int v = 0; v < 4; v++){
                const int r  = r_lo + ((v >= 2) ? 8 : 0);
                const int cc = wn*72 + nt*8 + 2*q + (v & 1);
                float sv = NEG;
                if (cc < NC){
                    int j = (cc < nglob) ? cc : jlo + (cc - nglob);
                    int i = i0 + r;
                    int d = i - j; if (d < 0) d = -d;
                    if (j < 4 || d <= 32) sv = cs[nt][v] * ATT_SCALE;
                }
                cs[nt][v] = sv;
            }

        float mlo = NEG, mhi = NEG;
        #pragma unroll
        for (int nt = 0; nt < 9; nt++){
            mlo = fmaxf(mlo, fmaxf(cs[nt][0], cs[nt][1]));
            mhi = fmaxf(mhi, fmaxf(cs[nt][2], cs[nt][3]));
        }
        mlo = fmaxf(mlo, __shfl_xor_sync(0xffffffffu, mlo, 1));
        mlo = fmaxf(mlo, __shfl_xor_sync(0xffffffffu, mlo, 2));
        mhi = fmaxf(mhi, __shfl_xor_sync(0xffffffffu, mhi, 1));
        mhi = fmaxf(mhi, __shfl_xor_sync(0xffffffffu, mhi, 2));
        if (q == 0){
            mred[wn*64 + r_lo]     = mlo;
            mred[wn*64 + r_lo + 8] = mhi;
        }
        __syncthreads();
        mlo = fmaxf(mred[r_lo],     mred[64 + r_lo]);
        mhi = fmaxf(mred[r_lo + 8], mred[64 + r_lo + 8]);

        float slo = 0.f, shi = 0.f;
        #pragma unroll
        for (int nt = 0; nt < 9; nt++){
            const int cc0 = wn*72 + nt*8 + 2*q;
            float p0 = __expf(cs[nt][0] - mlo);
            float p1 = __expf(cs[nt][1] - mlo);
            float p2 = __expf(cs[nt][2] - mhi);
            float p3 = __expf(cs[nt][3] - mhi);
            slo += p0 + p1; shi += p2 + p3;
            *(__half2*)&Ps[(r_lo    ) * PS_STR + cc0] = __floats2half2_rn(p0, p1);
            *(__half2*)&Ps[(r_lo + 8) * PS_STR + cc0] = __floats2half2_rn(p2, p3);
        }
        slo += __shfl_xor_sync(0xffffffffu, slo, 1);
        slo += __shfl_xor_sync(0xffffffffu, slo, 2);
        shi += __shfl_xor_sync(0xffffffffu, shi, 1);
        shi += __shfl_xor_sync(0xffffffffu, shi, 2);
        if (q == 0){
            sred[wn*64 + r_lo]     = slo;
            sred[wn*64 + r_lo + 8] = shi;
        }
    }
    __syncthreads();

    // ---- PV ----
    {
        const int wm2 = warp >> 1, wn2 = warp & 1;
        const int r_lo = wm2*16 + (lane >> 2);
        float co[4][4];
        #pragma unroll
        for (int nt = 0; nt < 4; nt++)
            #pragma unroll
            for (int v = 0; v < 4; v++) co[nt][v] = 0.f;

        #pragma unroll
        for (int ks = 0; ks < 9; ks++){
            const int k0 = ks * 16;
            uint32_t pa[4];
            pa[0] = *(const uint32_t*)&Ps[(r_lo    ) * PS_STR + k0 + 2*q];
            pa[1] = *(const uint32_t*)&Ps[(r_lo + 8) * PS_STR + k0 + 2*q];
            pa[2] = *(const uint32_t*)&Ps[(r_lo    ) * PS_STR + k0 + 8 + 2*q];
            pa[3] = *(const uint32_t*)&Ps[(r_lo + 8) * PS_STR + k0 + 8 + 2*q];
            uint32_t vb[2][4];
            #pragma unroll
            for (int db = 0; db < 2; db++){
                int m_ = lane >> 3;
                int j  = k0 + (lane & 7) + (m_ & 1) * 8;
                int dc = wn2*32 + db*16 + (m_ >> 1) * 8;
                ldm4t(vb[db], uV + SWZ((uint32_t)(j * 128 + dc * 2)));
            }
            #pragma unroll
            for (int nt = 0; nt < 4; nt++){
                const int db = nt >> 1, hi = nt & 1;
                mma16(co[nt], pa, vb[db][hi*2], vb[db][hi*2 + 1]);
            }
        }

        const float rlo = 1.f / (sred[r_lo]     + sred[64 + r_lo]);
        const float rhi = 1.f / (sred[r_lo + 8] + sred[64 + r_lo + 8]);
        #pragma unroll
        for (int nt = 0; nt < 4; nt++){
            const int d0 = wn2*32 + nt*8 + 2*q;
            #pragma unroll
            for (int hf = 0; hf < 2; hf++){
                const int r = r_lo + hf*8;
                const int i = i0 + r;
                if (i >= 4){
                    float sc = hf ? rhi : rlo;
                    __half2 hv = __floats2half2_rn(co[nt][hf*2] * sc, co[nt][hf*2+1] * sc);
                    *(__half2*)(g_att + base + (size_t)i * HD + d0) = hv;
                }
            }
        }
    }
}

// ---------------------------------------------------------------------------
// Global rows (i < 4): dense attention over all 2048 cols, fp32 math.
// One block per (row, head, batch) — 256 blocks (R4 layout; R5's 64-block
// fusion under-occupied the chip and regressed).
// ---------------------------------------------------------------------------
__global__ void __launch_bounds__(256)
attn_global()
{
    __shared__ float qs[HD];
    __shared__ float s[SEQ];
    __shared__ float red[256];
    const int tid = threadIdx.x;
    const int r = blockIdx.x, h = blockIdx.y, b = blockIdx.z;
    const size_t base = ((size_t)(b * NH + h)) * SEQ * HD;

    if (tid < HD) qs[tid] = __half2float(g_q[base + (size_t)r * HD + tid]);
    __syncthreads();

    for (int j = tid; j < SEQ; j += 256){
        const __half2* kr = (const __half2*)(g_k + base + (size_t)j * HD);
        float acc = 0.f;
        #pragma unroll
        for (int dd = 0; dd < 32; dd++){
            float2 kv = __half22float2(kr[dd]);
            acc += qs[2*dd] * kv.x + qs[2*dd+1] * kv.y;
        }
        s[j] = acc * ATT_SCALE;
    }
    __syncthreads();

    float lm = NEG;
    for (int j = tid; j < SEQ; j += 256) lm = fmaxf(lm, s[j]);
    red[tid] = lm; __syncthreads();
    for (int off = 128; off; off >>= 1){
        if (tid < off) red[tid] = fmaxf(red[tid], red[tid + off]);
        __syncthreads();
    }
    const float mx = red[0]; __syncthreads();

    float ls = 0.f;
    for (int j = tid; j < SEQ; j += 256){
        float p = __expf(s[j] - mx); s[j] = p; ls += p;
    }
    red[tid] = ls; __syncthreads();
    for (int off = 128; off; off >>= 1){
        if (tid < off) red[tid] += red[tid + off];
        __syncthreads();
    }
    const float ri = 1.f / red[0]; __syncthreads();

    const int d = tid & 63, ch = tid >> 6;
    float acc = 0.f;
    const __half* vb = g_v + base + d;
    for (int j = ch * 512; j < ch * 512 + 512; j++)
        acc += s[j] * __half2float(vb[(size_t)j * HD]);
    red[tid] = acc; __syncthreads();
    if (tid < 64)
        g_att[base + (size_t)r * HD + tid] = __float2half_rn(
            (red[tid] + red[tid + 64] + red[tid + 128] + red[tid + 192]) * ri);
}

// ---------------------------------------------------------------------------
extern "C" void kernel_launch(void* const* d_in, const int* in_sizes, int n_in,
                              void* d_out, int out_size)
{
    const float* x  = (const float*)d_in[0];
    const float* Wq = (const float*)d_in[1];
    const float* bq = (const float*)d_in[2];
    const float* Wk = (const float*)d_in[3];
    const float* bk = (const float*)d_in[4];
    const float* Wv = (const float*)d_in[5];
    const float* bv = (const float*)d_in[6];
    const float* Wo = (const float*)d_in[7];
    const float* bo = (const float*)d_in[8];
    float* out = (float*)d_out;

    const int gsm = NSTG * STG;     // 147456 B
    cudaFuncSetAttribute(gemm_h,    cudaFuncAttributeMaxDynamicSharedMemorySize, gsm);
    cudaFuncSetAttribute(attn_band, cudaFuncAttributeMaxDynamicSharedMemorySize, ATT_SMEM);

    conv_x<<<(MTOT*HID/8 + 255)/256, 256>>>(x, MTOT*HID/8);
    conv_w<<<dim3(HID*HID/8/256, 4), 256>>>(Wq, Wk, Wv, Wo);

    // fused QKV projections
    gemm_h<<<dim3(HID/GBN, MTOT/128, 3), GT, gsm>>>(bq, bk, bv, nullptr, 1);

    // attention
    attn_band<<<dim3(SEQ/64, NH, NB), 256, ATT_SMEM>>>();
    attn_global<<<dim3(4, NH, NB), 256>>>();

    // output projection
    gemm_h<<<dim3(HID/GBN, MTOT/128, 1), GT, gsm>>>(bo, nullptr, nullptr, out, 0);
}

// round 7
// speedup vs baseline: 1.0984x; 1.0702x over previous
#include <cuda_runtime.h>
#include <cuda_fp16.h>
#include <cstdint>

#define SEQ 2048
#define NB 4
#define NH 16
#define HD 64
#define HID 1024
#define MTOT (NB*SEQ)
#define NEG -1e30f
#define ATT_SCALE 0.125f

// ---------------- scratch (device globals; allocation-free rule) ----------
// dense [MTOT, HID] layouts: row = b*SEQ + s, col = h*HD + d
__device__ __half q_d[(size_t)MTOT*HID];
__device__ __half k_d[(size_t)MTOT*HID];
__device__ __half v_d[(size_t)MTOT*HID];
__device__ __half att_d[(size_t)MTOT*HID];
__device__ __half x_h[(size_t)MTOT*HID];
__device__ __half w_h[4*(size_t)HID*HID];

// ---------------- helpers -------------------------------------------------
__device__ __forceinline__ uint32_t smem_u32(const void* p){
    uint32_t a;
    asm("{ .reg .u64 t; cvta.to.shared.u64 t, %1; cvt.u32.u64 %0, t; }" : "=r"(a) : "l"(p));
    return a;
}
#define SWZ(b) ((b) ^ (((b) >> 3) & 0x70))

__device__ __forceinline__ void cp16s(uint32_t saddr, const void* g){
    asm volatile("cp.async.cg.shared.global [%0], [%1], 16;\n" :: "r"(saddr), "l"(g));
}
__device__ __forceinline__ void cp16z(uint32_t saddr, const void* g, int pred){
    int sz = pred ? 16 : 0;
    asm volatile("cp.async.cg.shared.global [%0], [%1], 16, %2;\n" :: "r"(saddr), "l"(g), "r"(sz));
}
__device__ __forceinline__ void ldm4(uint32_t* r, uint32_t addr){
    asm volatile("ldmatrix.sync.aligned.m8n8.x4.shared.b16 {%0,%1,%2,%3}, [%4];"
        : "=r"(r[0]),"=r"(r[1]),"=r"(r[2]),"=r"(r[3]) : "r"(addr));
}
__device__ __forceinline__ void ldm2(uint32_t* r, uint32_t addr){
    asm volatile("ldmatrix.sync.aligned.m8n8.x2.shared.b16 {%0,%1}, [%2];"
        : "=r"(r[0]),"=r"(r[1]) : "r"(addr));
}
__device__ __forceinline__ void ldm4t(uint32_t* r, uint32_t addr){
    asm volatile("ldmatrix.sync.aligned.m8n8.x4.trans.shared.b16 {%0,%1,%2,%3}, [%4];"
        : "=r"(r[0]),"=r"(r[1]),"=r"(r[2]),"=r"(r[3]) : "r"(addr));
}
__device__ __forceinline__ void mma16(float* c, const uint32_t* a, uint32_t b0, uint32_t b1){
    asm volatile(
      "mma.sync.aligned.m16n8k16.row.col.f32.f16.f16.f32 "
      "{%0,%1,%2,%3},{%4,%5,%6,%7},{%8,%9},{%0,%1,%2,%3};\n"
      : "+f"(c[0]), "+f"(c[1]), "+f"(c[2]), "+f"(c[3])
      : "r"(a[0]), "r"(a[1]), "r"(a[2]), "r"(a[3]), "r"(b0), "r"(b1));
}
__device__ __forceinline__ uint32_t frag_addr(uint32_t tile, int row0, int k0, int lane){
    int r = row0 + (lane & 7) + ((lane >> 3) & 1) * 8;
    int c = k0 + ((lane >> 4) << 3);
    return tile + SWZ((uint32_t)(r * 128 + c * 2));
}

// ---------------------------------------------------------------------------
// fp32 -> fp16 conversion prepass.
// ---------------------------------------------------------------------------
__global__ void __launch_bounds__(256)
conv_x(const float* __restrict__ src, int n8)
{
    int i = blockIdx.x * 256 + threadIdx.x;
    if (i < n8){
        float4 v0 = ((const float4*)src)[2*i];
        float4 v1 = ((const float4*)src)[2*i+1];
        __half2 h0 = __floats2half2_rn(v0.x, v0.y);
        __half2 h1 = __floats2half2_rn(v0.z, v0.w);
        __half2 h2 = __floats2half2_rn(v1.x, v1.y);
        __half2 h3 = __floats2half2_rn(v1.z, v1.w);
        uint2 o0, o1;
        o0.x = *(uint32_t*)&h0; o0.y = *(uint32_t*)&h1;
        o1.x = *(uint32_t*)&h2; o1.y = *(uint32_t*)&h3;
        ((uint2*)x_h)[2*i]   = o0;
        ((uint2*)x_h)[2*i+1] = o1;
    }
}

__global__ void __launch_bounds__(256)
conv_w(const float* __restrict__ w0, const float* __restrict__ w1,
       const float* __restrict__ w2, const float* __restrict__ w3)
{
    const int sel = blockIdx.y;
    const float* src = (sel==0) ? w0 : (sel==1 ? w1 : (sel==2 ? w2 : w3));
    __half* dst = w_h + (size_t)sel * (HID*HID);
    int i = blockIdx.x * 256 + threadIdx.x;
    float4 v0 = ((const float4*)src)[2*i];
    float4 v1 = ((const float4*)src)[2*i+1];
    __half2 h0 = __floats2half2_rn(v0.x, v0.y);
    __half2 h1 = __floats2half2_rn(v0.z, v0.w);
    __half2 h2 = __floats2half2_rn(v1.x, v1.y);
    __half2 h3 = __floats2half2_rn(v1.z, v1.w);
    uint2 o0, o1;
    o0.x = *(uint32_t*)&h0; o0.y = *(uint32_t*)&h1;
    o1.x = *(uint32_t*)&h2; o1.y = *(uint32_t*)&h3;
    ((uint2*)dst)[2*i]   = o0;
    ((uint2*)dst)[2*i+1] = o1;
}

// ---------------------------------------------------------------------------
// fp16 GEMM:  Y[M,N] = A[M,K] @ W[N,K]^T + bias     (R4 config: fastest so far)
// BM=128 BN=128 BK=64, 256 threads (8 warps, 4m x 2n), 2 CTAs/SM,
// 3-stage cp.async, SW128 smem, ldmatrix + mma.m16n8k16.
// A is always a dense [M, HID] half matrix (x_h or att_d).
// qkv_mode=1: dst = q_d/k_d/v_d (dense half) via staged smem epilogue.
// qkv_mode=0: dst = fp32 out (dense) + bias.
// ---------------------------------------------------------------------------
#define GBK 64
#define A_BYT (128*128)         // 16 KB
#define STG   (2*A_BYT)         // 32 KB per stage
#define NSTG  3
#define NK    (HID/GBK)         // 16

__global__ void __launch_bounds__(256, 2)
gemm_h(const __half* __restrict__ A,
       const float* __restrict__ b0_, const float* __restrict__ b1_,
       const float* __restrict__ b2_, float* __restrict__ Yout, int qkv_mode)
{
    extern __shared__ char smem[];
    const uint32_t sb0 = smem_u32(smem);
    const int tid = threadIdx.x, lane = tid & 31, warp = tid >> 5;
    const int wm = warp & 3, wn = warp >> 2;            // 4m x 2n warps
    const int n0 = blockIdx.x * 128, m0 = blockIdx.y * 128;
    const int z  = qkv_mode ? blockIdx.z : 3;
    const __half* W    = w_h + (size_t)z * (HID*HID);
    const float* bias  = qkv_mode ? (z==0 ? b0_ : (z==1 ? b1_ : b2_)) : b0_;
    __half* dsth       = qkv_mode ? (z==0 ? q_d : (z==1 ? k_d : v_d)) : nullptr;

    float c[2][8][4];
    #pragma unroll
    for (int i = 0; i < 2; i++)
      #pragma unroll
      for (int j = 0; j < 8; j++)
        #pragma unroll
        for (int v = 0; v < 4; v++) c[i][j][v] = 0.f;

    auto load_chunk = [&](int ch, int slot){
        const int k0 = ch * GBK;
        const uint32_t uA = sb0 + slot * STG;
        const uint32_t uB = uA + A_BYT;
        #pragma unroll
        for (int i = 0; i < 4; i++){                    // A: 1024 16B ops
            int op = tid + i * 256;
            int row = op >> 3, at = op & 7;
            cp16s(uA + SWZ((uint32_t)(row * 128 + at * 16)),
                  A + (size_t)(m0 + row) * HID + k0 + at * 8);
        }
        #pragma unroll
        for (int i = 0; i < 4; i++){                    // B: 1024 16B ops
            int op = tid + i * 256;
            int row = op >> 3, at = op & 7;
            cp16s(uB + SWZ((uint32_t)(row * 128 + at * 16)),
                  W + (size_t)(n0 + row) * HID + k0 + at * 8);
        }
        asm volatile("cp.async.commit_group;\n");
    };

    load_chunk(0, 0);
    load_chunk(1, 1);

    for (int ch = 0; ch < NK; ch++){
        if (ch + 2 < NK) load_chunk(ch + 2, (ch + 2) % NSTG);
        const int rem = NK - 1 - ch;
        if      (rem >= 2) asm volatile("cp.async.wait_group 2;\n");
        else if (rem == 1) asm volatile("cp.async.wait_group 1;\n");
        else               asm volatile("cp.async.wait_group 0;\n");
        __syncthreads();

        const uint32_t uA = sb0 + (ch % NSTG) * STG;
        const uint32_t uB = uA + A_BYT;
        #pragma unroll
        for (int ks = 0; ks < 4; ks++){
            uint32_t a[2][4];
            ldm4(a[0], frag_addr(uA, wm*32,      ks*16, lane));
            ldm4(a[1], frag_addr(uA, wm*32 + 16, ks*16, lane));
            uint32_t b[4][4];
            #pragma unroll
            for (int nb = 0; nb < 4; nb++)
                ldm4(b[nb], frag_addr(uB, wn*64 + nb*16, ks*16, lane));
            #pragma unroll
            for (int nt = 0; nt < 8; nt++){
                const int nb = nt >> 1, hi = nt & 1;
                mma16(c[0][nt], a[0], b[nb][hi], b[nb][2+hi]);
                mma16(c[1][nt], a[1], b[nb][hi], b[nb][2+hi]);
            }
        }
        __syncthreads();
    }

    if (qkv_mode){
        // staged epilogue: frags -> smem (half) -> fully coalesced 16B stores
        __half* stg = (__half*)smem;                    // 128 x 136 halves
        #pragma unroll
        for (int nt = 0; nt < 8; nt++){
            const int cn = wn*64 + nt*8 + 2*(lane & 3);
            float2 bv = *(const float2*)(bias + n0 + cn);
            #pragma unroll
            for (int mt = 0; mt < 2; mt++){
                const int r0 = wm*32 + mt*16 + (lane >> 2);
                #pragma unroll
                for (int hf = 0; hf < 2; hf++){
                    *(__half2*)&stg[(r0 + hf*8) * 136 + cn] =
                        __floats2half2_rn(c[mt][nt][hf*2] + bv.x,
                                          c[mt][nt][hf*2+1] + bv.y);
                }
            }
        }
        __syncthreads();
        #pragma unroll
        for (int i = 0; i < 8; i++){                    // 2048 16B slots
            int op = tid + i * 256;
            int row = op >> 4, c16 = op & 15;
            uint4 val = *(const uint4*)&stg[row * 136 + c16 * 8];
            *(uint4*)(dsth + (size_t)(m0 + row) * HID + n0 + c16 * 8) = val;
        }
    } else {
        #pragma unroll
        for (int nt = 0; nt < 8; nt++){
            const int nn = n0 + wn*64 + nt*8 + 2*(lane & 3);
            float2 bv = *(const float2*)(bias + nn);
            #pragma unroll
            for (int mt = 0; mt < 2; mt++){
                const int rr = m0 + wm*32 + mt*16 + (lane >> 2);
                #pragma unroll
                for (int hf = 0; hf < 2; hf++){
                    const int m = rr + hf*8;
                    *(float2*)(Yout + (size_t)m * HID + nn) =
                        make_float2(c[mt][nt][hf*2] + bv.x, c[mt][nt][hf*2+1] + bv.y);
                }
            }
        }
    }
}

// ---------------------------------------------------------------------------
// Band attention, fp16 mma: one block per (64-row tile, head, batch).
// Dense [M, HID] scratch addressing.
// ---------------------------------------------------------------------------
#define PS_STR 168
#define QS_OFF 0
#define KS_OFF 8192
#define VS_OFF 26624
#define PS_OFF 45056
#define RED_OFF 66560
#define ATT_SMEM (RED_OFF + 1024)

__global__ void __launch_bounds__(256, 3)
attn_band()
{
    extern __shared__ char smem[];
    const uint32_t sb = smem_u32(smem);
    const uint32_t uQ = sb + QS_OFF, uK = sb + KS_OFF, uV = sb + VS_OFF;
    __half* Ps  = (__half*)(smem + PS_OFF);
    float* mred = (float*)(smem + RED_OFF);      // [2][64]
    float* sred = mred + 128;                    // [2][64]

    const int tid = threadIdx.x, lane = tid & 31, warp = tid >> 5;
    const int q = lane & 3;
    const int t = blockIdx.x, h = blockIdx.y, b = blockIdx.z;
    const int i0 = t * 64;
    const int nglob = (t == 0) ? 0 : 4;
    const int jlo   = (t == 0) ? 0 : (i0 - 32);
    const int jhi   = min(SEQ - 1, i0 + 95);
    const int NC    = nglob + (jhi - jlo + 1);
    const size_t rbase = (size_t)b * SEQ * HID + h * HD;   // + s*HID + d

    #pragma unroll
    for (int i = 0; i < 2; i++){
        int op = tid + i * 256;
        int row = op >> 3, at = op & 7;
        cp16s(uQ + SWZ((uint32_t)(row * 128 + at * 16)),
              q_d + rbase + (size_t)(i0 + row) * HID + at * 8);
    }
    #pragma unroll
    for (int i = 0; i < 9; i++){
        int op = tid + i * 256;
        int cc = op >> 4, at8 = op & 15;
        int at = at8 & 7;
        int isK = (at8 < 8);
        int valid = (cc < NC);
        int j = valid ? ((cc < nglob) ? cc : jlo + (cc - nglob)) : 0;
        const __half* src = (isK ? k_d : v_d) + rbase + (size_t)j * HID + at * 8;
        cp16z((isK ? uK : uV) + SWZ((uint32_t)(cc * 128 + at * 16)), src, valid);
    }
    asm volatile("cp.async.commit_group;\ncp.async.wait_group 0;\n");
    __syncthreads();

    // ---- scores ----
    {
        const int wm = warp >> 1, wn = warp & 1;
        const int r_lo = wm*16 + (lane >> 2);
        float cs[9][4];
        #pragma unroll
        for (int nt = 0; nt < 9; nt++)
            #pragma unroll
            for (int v = 0; v < 4; v++) cs[nt][v] = 0.f;

        #pragma unroll
        for (int ks = 0; ks < 4; ks++){
            uint32_t qa[4];
            ldm4(qa, frag_addr(uQ, wm*16, ks*16, lane));
            uint32_t kb[4][4];
            #pragma unroll
            for (int nb = 0; nb < 4; nb++)
                ldm4(kb[nb], frag_addr(uK, wn*72 + nb*16, ks*16, lane));
            uint32_t k2[2];
            {
                int i2 = lane & 15;
                int rr = wn*72 + 64 + (i2 & 7);
                int cc = ks*16 + ((i2 >> 3) << 3);
                ldm2(k2, uK + SWZ((uint32_t)(rr * 128 + cc * 2)));
            }
            #pragma unroll
            for (int nt = 0; nt < 8; nt++){
                const int nb = nt >> 1, hi = nt & 1;
                mma16(cs[nt], qa, kb[nb][hi], kb[nb][2+hi]);
            }
            mma16(cs[8], qa, k2[0], k2[1]);
        }

        #pragma unroll
        for (int nt = 0; nt < 9; nt++)
            #pragma unroll
            for (int v = 0; v < 4; v++){
                const int r  = r_lo + ((v >= 2) ? 8 : 0);
                const int cc = wn*72 + nt*8 + 2*q + (v & 1);
                float sv = NEG;
                if (cc < NC){
                    int j = (cc < nglob) ? cc : jlo + (cc - nglob);
                    int i = i0 + r;
                    int d = i - j; if (d < 0) d = -d;
                    if (j < 4 || d <= 32) sv = cs[nt][v] * ATT_SCALE;
                }
                cs[nt][v] = sv;
            }

        float mlo = NEG, mhi = NEG;
        #pragma unroll
        for (int nt = 0; nt < 9; nt++){
            mlo = fmaxf(mlo, fmaxf(cs[nt][0], cs[nt][1]));
            mhi = fmaxf(mhi, fmaxf(cs[nt][2], cs[nt][3]));
        }
        mlo = fmaxf(mlo, __shfl_xor_sync(0xffffffffu, mlo, 1));
        mlo = fmaxf(mlo, __shfl_xor_sync(0xffffffffu, mlo, 2));
        mhi = fmaxf(mhi, __shfl_xor_sync(0xffffffffu, mhi, 1));
        mhi = fmaxf(mhi, __shfl_xor_sync(0xffffffffu, mhi, 2));
        if (q == 0){
            mred[wn*64 + r_lo]     = mlo;
            mred[wn*64 + r_lo + 8] = mhi;
        }
        __syncthreads();
        mlo = fmaxf(mred[r_lo],     mred[64 + r_lo]);
        mhi = fmaxf(mred[r_lo + 8], mred[64 + r_lo + 8]);

        float slo = 0.f, shi = 0.f;
        #pragma unroll
        for (int nt = 0; nt < 9; nt++){
            const int cc0 = wn*72 + nt*8 + 2*q;
            float p0 = __expf(cs[nt][0] - mlo);
            float p1 = __expf(cs[nt][1] - mlo);
            float p2 = __expf(cs[nt][2] - mhi);
            float p3 = __expf(cs[nt][3] - mhi);
            slo += p0 + p1; shi += p2 + p3;
            *(__half2*)&Ps[(r_lo    ) * PS_STR + cc0] = __floats2half2_rn(p0, p1);
            *(__half2*)&Ps[(r_lo + 8) * PS_STR + cc0] = __floats2half2_rn(p2, p3);
        }
        slo += __shfl_xor_sync(0xffffffffu, slo, 1);
        slo += __shfl_xor_sync(0xffffffffu, slo, 2);
        shi += __shfl_xor_sync(0xffffffffu, shi, 1);
        shi += __shfl_xor_sync(0xffffffffu, shi, 2);
        if (q == 0){
            sred[wn*64 + r_lo]     = slo;
            sred[wn*64 + r_lo + 8] = shi;
        }
    }
    __syncthreads();

    // ---- PV ----
    {
        const int wm2 = warp >> 1, wn2 = warp & 1;
        const int r_lo = wm2*16 + (lane >> 2);
        float co[4][4];
        #pragma unroll
        for (int nt = 0; nt < 4; nt++)
            #pragma unroll
            for (int v = 0; v < 4; v++) co[nt][v] = 0.f;

        #pragma unroll
        for (int ks = 0; ks < 9; ks++){
            const int k0 = ks * 16;
            uint32_t pa[4];
            pa[0] = *(const uint32_t*)&Ps[(r_lo    ) * PS_STR + k0 + 2*q];
            pa[1] = *(const uint32_t*)&Ps[(r_lo + 8) * PS_STR + k0 + 2*q];
            pa[2] = *(const uint32_t*)&Ps[(r_lo    ) * PS_STR + k0 + 8 + 2*q];
            pa[3] = *(const uint32_t*)&Ps[(r_lo + 8) * PS_STR + k0 + 8 + 2*q];
            uint32_t vb[2][4];
            #pragma unroll
            for (int db = 0; db < 2; db++){
                int m_ = lane >> 3;
                int j  = k0 + (lane & 7) + (m_ & 1) * 8;
                int dc = wn2*32 + db*16 + (m_ >> 1) * 8;
                ldm4t(vb[db], uV + SWZ((uint32_t)(j * 128 + dc * 2)));
            }
            #pragma unroll
            for (int nt = 0; nt < 4; nt++){
                const int db = nt >> 1, hi = nt & 1;
                mma16(co[nt], pa, vb[db][hi*2], vb[db][hi*2 + 1]);
            }
        }

        const float rlo = 1.f / (sred[r_lo]     + sred[64 + r_lo]);
        const float rhi = 1.f / (sred[r_lo + 8] + sred[64 + r_lo + 8]);
        #pragma unroll
        for (int nt = 0; nt < 4; nt++){
            const int d0 = wn2*32 + nt*8 + 2*q;
            #pragma unroll
            for (int hf = 0; hf < 2; hf++){
                const int r = r_lo + hf*8;
                const int i = i0 + r;
                if (i >= 4){
                    float sc = hf ? rhi : rlo;
                    __half2 hv = __floats2half2_rn(co[nt][hf*2] * sc, co[nt][hf*2+1] * sc);
                    *(__half2*)(att_d + rbase + (size_t)i * HID + d0) = hv;
                }
            }
        }
    }
}

// ---------------------------------------------------------------------------
// Global rows (i < 4): dense attention over all 2048 cols, fp32 math.
// One block per (row, head, batch) — 256 blocks.
// ---------------------------------------------------------------------------
__global__ void __launch_bounds__(256)
attn_global()
{
    __shared__ float qs[HD];
    __shared__ float s[SEQ];
    __shared__ float red[256];
    const int tid = threadIdx.x;
    const int r = blockIdx.x, h = blockIdx.y, b = blockIdx.z;
    const size_t rbase = (size_t)b * SEQ * HID + h * HD;

    if (tid < HD) qs[tid] = __half2float(q_d[rbase + (size_t)r * HID + tid]);
    __syncthreads();

    for (int j = tid; j < SEQ; j += 256){
        const __half2* kr = (const __half2*)(k_d + rbase + (size_t)j * HID);
        float acc = 0.f;
        #pragma unroll
        for (int dd = 0; dd < 32; dd++){
            float2 kv = __half22float2(kr[dd]);
            acc += qs[2*dd] * kv.x + qs[2*dd+1] * kv.y;
        }
        s[j] = acc * ATT_SCALE;
    }
    __syncthreads();

    float lm = NEG;
    for (int j = tid; j < SEQ; j += 256) lm = fmaxf(lm, s[j]);
    red[tid] = lm; __syncthreads();
    for (int off = 128; off; off >>= 1){
        if (tid < off) red[tid] = fmaxf(red[tid], red[tid + off]);
        __syncthreads();
    }
    const float mx = red[0]; __syncthreads();

    float ls = 0.f;
    for (int j = tid; j < SEQ; j += 256){
        float p = __expf(s[j] - mx); s[j] = p; ls += p;
    }
    red[tid] = ls; __syncthreads();
    for (int off = 128; off; off >>= 1){
        if (tid < off) red[tid] += red[tid + off];
        __syncthreads();
    }
    const float ri = 1.f / red[0]; __syncthreads();

    const int d = tid & 63, ch = tid >> 6;
    float acc = 0.f;
    const __half* vb = v_d + rbase + d;
    for (int j = ch * 512; j < ch * 512 + 512; j++)
        acc += s[j] * __half2float(vb[(size_t)j * HID]);
    red[tid] = acc; __syncthreads();
    if (tid < 64)
        att_d[rbase + (size_t)r * HID + tid] = __float2half_rn(
            (red[tid] + red[tid + 64] + red[tid + 128] + red[tid + 192]) * ri);
}

// ---------------------------------------------------------------------------
extern "C" void kernel_launch(void* const* d_in, const int* in_sizes, int n_in,
                              void* d_out, int out_size)
{
    const float* x  = (const float*)d_in[0];
    const float* bq = (const float*)d_in[2];
    const float* Wq = (const float*)d_in[1];
    const float* Wk = (const float*)d_in[3];
    const float* bk = (const float*)d_in[4];
    const float* Wv = (const float*)d_in[5];
    const float* bv = (const float*)d_in[6];
    const float* Wo = (const float*)d_in[7];
    const float* bo = (const float*)d_in[8];
    float* out = (float*)d_out;

    const int gsm = NSTG * STG;     // 98304 B
    cudaFuncSetAttribute(gemm_h,    cudaFuncAttributeMaxDynamicSharedMemorySize, gsm);
    cudaFuncSetAttribute(attn_band, cudaFuncAttributeMaxDynamicSharedMemorySize, ATT_SMEM);

    // dense half pointers needed at device-symbol addresses: get via kernels'
    // own references (device globals are directly addressable in kernels).
    conv_x<<<(MTOT*HID/8 + 255)/256, 256>>>(x, MTOT*HID/8);
    conv_w<<<dim3(HID*HID/8/256, 4), 256>>>(Wq, Wk, Wv, Wo);

    // fused QKV projections (A = x_h; pass nullptr, kernel uses x via param)
    {
        // obtain device pointers to __device__ globals without cudaMalloc:
        // use cudaGetSymbolAddress (host API, allowed — no allocation).
        static __half* p_xh = nullptr;
        static __half* p_att = nullptr;
        if (!p_xh){
            void* tmp;
            cudaGetSymbolAddress(&tmp, x_h);  p_xh  = (__half*)tmp;
            cudaGetSymbolAddress(&tmp, att_d); p_att = (__half*)tmp;
        }
        gemm_h<<<dim3(HID/128, MTOT/128, 3), 256, gsm>>>(p_xh, bq, bk, bv, nullptr, 1);

        attn_band<<<dim3(SEQ/64, NH, NB), 256, ATT_SMEM>>>();
        attn_global<<<dim3(4, NH, NB), 256>>>();

        gemm_h<<<dim3(HID/128, MTOT/128, 1), 256, gsm>>>(p_att, bo, nullptr, nullptr, out, 0);
    }
}